// round 1
// baseline (speedup 1.0000x reference)
#include <cuda_runtime.h>
#include <math.h>

// Problem constants
#define Bsz   4096
#define Tt    512
#define INP   25
#define Hh    50
#define Gg    200          // 4*H, gate order i,f,g,o
#define ROWS  28           // batch rows per CTA
#define NTH   352          // threads per CTA (11 warps)
#define CG    50           // column groups of 4 (200/4)
#define NTASK 350          // CG * (ROWS/4)
#define GRID  147          // 146*28 + 8 = 4096

__device__ __forceinline__ float sigf(float v) {
    return 1.0f / (1.0f + __expf(-v));
}
__device__ __forceinline__ float tanh_fast(float v) {
    // tanh(x) = 2*sigmoid(2x) - 1
    return fmaf(2.0f, 1.0f / (1.0f + __expf(-2.0f * v)), -1.0f);
}

#define FMA16(w, hv)                                                       \
    acc[0][0] = fmaf(w.x, hv.x, acc[0][0]);                                \
    acc[0][1] = fmaf(w.x, hv.y, acc[0][1]);                                \
    acc[0][2] = fmaf(w.x, hv.z, acc[0][2]);                                \
    acc[0][3] = fmaf(w.x, hv.w, acc[0][3]);                                \
    acc[1][0] = fmaf(w.y, hv.x, acc[1][0]);                                \
    acc[1][1] = fmaf(w.y, hv.y, acc[1][1]);                                \
    acc[1][2] = fmaf(w.y, hv.z, acc[1][2]);                                \
    acc[1][3] = fmaf(w.y, hv.w, acc[1][3]);                                \
    acc[2][0] = fmaf(w.z, hv.x, acc[2][0]);                                \
    acc[2][1] = fmaf(w.z, hv.y, acc[2][1]);                                \
    acc[2][2] = fmaf(w.z, hv.z, acc[2][2]);                                \
    acc[2][3] = fmaf(w.z, hv.w, acc[2][3]);                                \
    acc[3][0] = fmaf(w.w, hv.x, acc[3][0]);                                \
    acc[3][1] = fmaf(w.w, hv.y, acc[3][1]);                                \
    acc[3][2] = fmaf(w.w, hv.z, acc[3][2]);                                \
    acc[3][3] = fmaf(w.w, hv.w, acc[3][3]);

__global__ void __launch_bounds__(NTH, 1)
bayes_lstm_kernel(const float* __restrict__ x,
                  const float* __restrict__ wi_mu, const float* __restrict__ wi_rho,
                  const float* __restrict__ wh_mu, const float* __restrict__ wh_rho,
                  const float* __restrict__ b_mu,  const float* __restrict__ b_rho,
                  const float* __restrict__ lin_w, const float* __restrict__ lin_b,
                  const float* __restrict__ eps_wi, const float* __restrict__ eps_wh,
                  const float* __restrict__ eps_b,
                  float* __restrict__ out)
{
    extern __shared__ float sm[];
    float* wi_s    = sm;                       // [INP][Gg]      5000
    float* wh_s    = wi_s + INP * Gg;          // [Hh][Gg]      10000
    float* bias_s  = wh_s + Hh * Gg;           // [Gg]            200
    float* h_s     = bias_s + Gg;              // [Hh][ROWS]     1400 (k-major, transposed)
    float* c_s     = h_s + Hh * ROWS;          // [Hh][ROWS]     1400
    float* gates_s = c_s + Hh * ROWS;          // [Gg][ROWS]     5600
    float* x_s     = gates_s + Gg * ROWS;      // [2][INP][ROWS] 1400 (double buffer, k-major)

    const int tid  = threadIdx.x;
    const long row0 = (long)blockIdx.x * ROWS;

    // ---- One-time: sample weights w = mu + softplus(rho) * eps into SMEM ----
    for (int i = tid; i < INP * Gg; i += NTH) {
        float sp = log1pf(__expf(wi_rho[i]));
        wi_s[i] = fmaf(sp, eps_wi[i], wi_mu[i]);
    }
    for (int i = tid; i < Hh * Gg; i += NTH) {
        float sp = log1pf(__expf(wh_rho[i]));
        wh_s[i] = fmaf(sp, eps_wh[i], wh_mu[i]);
    }
    for (int i = tid; i < Gg; i += NTH) {
        float sp = log1pf(__expf(b_rho[i]));
        bias_s[i] = fmaf(sp, eps_b[i], b_mu[i]);
    }
    for (int i = tid; i < Hh * ROWS; i += NTH) { h_s[i] = 0.0f; c_s[i] = 0.0f; }

    // x for t = 0 (transposed into x_s[0][k][r]); consecutive tid -> consecutive k (coalesced-ish)
    for (int i = tid; i < INP * ROWS; i += NTH) {
        int r = i / INP, k = i % INP;
        float v = 0.0f;
        if (row0 + r < Bsz) v = x[(size_t)(row0 + r) * (Tt * INP) + k];
        x_s[k * ROWS + r] = v;
    }
    __syncthreads();

    // Gate-phase task decomposition: 4 cols x 4 rows per thread
    const int  cg   = tid % CG;
    const int  rg   = tid / CG;
    const int  j0   = cg * 4;
    const int  rr0  = rg * 4;
    const bool active = (tid < NTASK);

    for (int t = 0; t < Tt; ++t) {
        const float* xcur = x_s + (t & 1) * (INP * ROWS);
        float*       xnxt = x_s + ((t + 1) & 1) * (INP * ROWS);

        // Issue next-step x loads early (latency hidden under gate compute)
        float pf0 = 0.0f, pf1 = 0.0f;
        const int p0 = tid, p1 = tid + NTH;
        if (t + 1 < Tt) {
            {
                int r = p0 / INP, k = p0 % INP;
                if (row0 + r < Bsz)
                    pf0 = x[(size_t)(row0 + r) * (Tt * INP) + (size_t)(t + 1) * INP + k];
            }
            if (p1 < INP * ROWS) {
                int r = p1 / INP, k = p1 % INP;
                if (row0 + r < Bsz)
                    pf1 = x[(size_t)(row0 + r) * (Tt * INP) + (size_t)(t + 1) * INP + k];
            }
        }

        // ---- Gate compute: gates[j0..j0+3][rr0..rr0+3] ----
        float acc[4][4];
        if (active) {
            #pragma unroll
            for (int u = 0; u < 4; u++) {
                float bv = bias_s[j0 + u];
                #pragma unroll
                for (int v = 0; v < 4; v++) acc[u][v] = bv;
            }
            // x_t @ wi  (K = 25)
            #pragma unroll 5
            for (int k = 0; k < INP; k++) {
                float4 w  = *(const float4*)(wi_s + k * Gg + j0);
                float4 hv = *(const float4*)(xcur + k * ROWS + rr0);
                FMA16(w, hv)
            }
            // h @ wh  (K = 50)
            #pragma unroll 5
            for (int k = 0; k < Hh; k++) {
                float4 w  = *(const float4*)(wh_s + k * Gg + j0);
                float4 hv = *(const float4*)(h_s + k * ROWS + rr0);
                FMA16(w, hv)
            }
            #pragma unroll
            for (int u = 0; u < 4; u++) {
                *(float4*)(gates_s + (j0 + u) * ROWS + rr0) =
                    make_float4(acc[u][0], acc[u][1], acc[u][2], acc[u][3]);
            }
        }

        // Commit prefetched x to the other buffer
        if (t + 1 < Tt) {
            { int r = p0 / INP, k = p0 % INP; xnxt[k * ROWS + r] = pf0; }
            if (p1 < INP * ROWS) { int r = p1 / INP, k = p1 % INP; xnxt[k * ROWS + r] = pf1; }
        }
        __syncthreads();

        // ---- Epilogue: activations + cell/hidden update ----
        for (int i = tid; i < Hh * ROWS; i += NTH) {
            float gi = gates_s[i];                     // i gate   (cols 0..49)
            float gf = gates_s[Hh * ROWS + i];         // f gate   (cols 50..99)
            float gg = gates_s[2 * Hh * ROWS + i];     // g gate   (cols 100..149)
            float go = gates_s[3 * Hh * ROWS + i];     // o gate   (cols 150..199)
            float iv = sigf(gi);
            float fv = sigf(gf);
            float gv = tanh_fast(gg);
            float ov = sigf(go);
            float c  = fmaf(fv, c_s[i], iv * gv);
            c_s[i] = c;
            h_s[i] = ov * tanh_fast(c);
        }
        __syncthreads();
    }

    // ---- Head: out[r] = h_last[r,:] . lin_w + lin_b ----
    for (int r = tid; r < ROWS; r += NTH) {
        if (row0 + r < Bsz) {
            float s = lin_b[0];
            #pragma unroll
            for (int m = 0; m < Hh; m++)
                s = fmaf(h_s[m * ROWS + r], lin_w[m], s);
            out[row0 + r] = s;
        }
    }
}

extern "C" void kernel_launch(void* const* d_in, const int* in_sizes, int n_in,
                              void* d_out, int out_size)
{
    const size_t smem_bytes =
        (size_t)(INP * Gg + Hh * Gg + Gg + 2 * Hh * ROWS + Gg * ROWS + 2 * INP * ROWS)
        * sizeof(float);  // 100000 B
    cudaFuncSetAttribute(bayes_lstm_kernel,
                         cudaFuncAttributeMaxDynamicSharedMemorySize,
                         (int)smem_bytes);
    bayes_lstm_kernel<<<GRID, NTH, smem_bytes>>>(
        (const float*)d_in[0],  (const float*)d_in[1],  (const float*)d_in[2],
        (const float*)d_in[3],  (const float*)d_in[4],  (const float*)d_in[5],
        (const float*)d_in[6],  (const float*)d_in[7],  (const float*)d_in[8],
        (const float*)d_in[9],  (const float*)d_in[10], (const float*)d_in[11],
        (float*)d_out);
}

// round 2
// speedup vs baseline: 1.0715x; 1.0715x over previous
#include <cuda_runtime.h>
#include <math.h>

// Problem constants
#define Bsz   4096
#define Tt    512
#define INP   25
#define Hh    50
#define Gg    200          // 4*H, gate order i,f,g,o
#define KTOT  75           // IN + H (fused contraction dim)
#define KSPL  37           // parity-0 threads do k in [0,37), parity-1 [37,75)
#define ROWS  28           // batch rows per CTA
#define NTH   704          // 22 warps
#define GRID  147          // 146*28 + 8 = 4096

__device__ __forceinline__ float sigf(float v) {
    return 1.0f / (1.0f + __expf(-v));
}
__device__ __forceinline__ float tanh_fast(float v) {
    return fmaf(2.0f, 1.0f / (1.0f + __expf(-2.0f * v)), -1.0f);
}

#define FMA16(w, hv)                                                       \
    acc[0][0] = fmaf(w.x, hv.x, acc[0][0]);                                \
    acc[0][1] = fmaf(w.x, hv.y, acc[0][1]);                                \
    acc[0][2] = fmaf(w.x, hv.z, acc[0][2]);                                \
    acc[0][3] = fmaf(w.x, hv.w, acc[0][3]);                                \
    acc[1][0] = fmaf(w.y, hv.x, acc[1][0]);                                \
    acc[1][1] = fmaf(w.y, hv.y, acc[1][1]);                                \
    acc[1][2] = fmaf(w.y, hv.z, acc[1][2]);                                \
    acc[1][3] = fmaf(w.y, hv.w, acc[1][3]);                                \
    acc[2][0] = fmaf(w.z, hv.x, acc[2][0]);                                \
    acc[2][1] = fmaf(w.z, hv.y, acc[2][1]);                                \
    acc[2][2] = fmaf(w.z, hv.z, acc[2][2]);                                \
    acc[2][3] = fmaf(w.z, hv.w, acc[2][3]);                                \
    acc[3][0] = fmaf(w.w, hv.x, acc[3][0]);                                \
    acc[3][1] = fmaf(w.w, hv.y, acc[3][1]);                                \
    acc[3][2] = fmaf(w.w, hv.z, acc[3][2]);                                \
    acc[3][3] = fmaf(w.w, hv.w, acc[3][3]);

__global__ void __launch_bounds__(NTH, 1)
bayes_lstm_kernel(const float* __restrict__ x,
                  const float* __restrict__ wi_mu, const float* __restrict__ wi_rho,
                  const float* __restrict__ wh_mu, const float* __restrict__ wh_rho,
                  const float* __restrict__ b_mu,  const float* __restrict__ b_rho,
                  const float* __restrict__ lin_w, const float* __restrict__ lin_b,
                  const float* __restrict__ eps_wi, const float* __restrict__ eps_wh,
                  const float* __restrict__ eps_b,
                  float* __restrict__ out)
{
    extern __shared__ float sm[];
    float* w_s     = sm;                       // [KTOT][Gg]   15000 (wi rows 0..24, wh rows 25..74)
    float* bias_s  = w_s + KTOT * Gg;          // [Gg]           200
    float* xh_s    = bias_s + Gg;              // [KTOT][ROWS]  2100 (x rows 0..24, h rows 25..74)
    float* c_s     = xh_s + KTOT * ROWS;       // [Hh][ROWS]    1400
    float* gates_s = c_s + Hh * ROWS;          // [Gg][ROWS]    5600

    const int tid  = threadIdx.x;
    const long row0 = (long)blockIdx.x * ROWS;

    // ---- One-time: sample fused weight matrix w = mu + softplus(rho) * eps ----
    for (int i = tid; i < KTOT * Gg; i += NTH) {
        float mu, rho, ep;
        if (i < INP * Gg) { mu = wi_mu[i]; rho = wi_rho[i]; ep = eps_wi[i]; }
        else { int j = i - INP * Gg; mu = wh_mu[j]; rho = wh_rho[j]; ep = eps_wh[j]; }
        float sp = log1pf(__expf(rho));
        w_s[i] = fmaf(sp, ep, mu);
    }
    for (int i = tid; i < Gg; i += NTH) {
        float sp = log1pf(__expf(b_rho[i]));
        bias_s[i] = fmaf(sp, eps_b[i], b_mu[i]);
    }
    // h rows of xh zero, c zero
    for (int i = tid; i < Hh * ROWS; i += NTH) {
        xh_s[INP * ROWS + i] = 0.0f;
        c_s[i] = 0.0f;
    }
    // x rows for t = 0: thread -> (r, k)
    {
        const int r = tid / INP, k = tid % INP;
        if (tid < INP * ROWS) {
            float v = 0.0f;
            if (row0 + r < Bsz) v = x[(size_t)(row0 + r) * (Tt * INP) + k];
            xh_s[k * ROWS + r] = v;
        }
    }
    __syncthreads();

    // Split-K task map: pair of lane-adjacent threads per 4x4 tile
    const bool store_ok = (tid < 700);
    const int  tile = store_ok ? (tid >> 1) : 349;
    const int  kh   = tid & 1;
    const int  j0   = (tile % 50) * 4;
    const int  rr0  = (tile / 50) * 4;
    const int  kbeg = kh ? KSPL : 0;
    const int  kend = kh ? KTOT : KSPL;

    // x prefetch map
    const int  pr = tid / INP, pk = tid % INP;
    const bool pf_ok = (tid < INP * ROWS) && (row0 + pr < Bsz);
    const size_t pf_base = pf_ok ? ((size_t)(row0 + pr) * (Tt * INP) + pk) : 0;

    for (int t = 0; t < Tt; ++t) {
        // Prefetch x(t+1) into a register (latency hidden under gate compute)
        float pf = 0.0f;
        if (pf_ok && t + 1 < Tt) pf = x[pf_base + (size_t)(t + 1) * INP];

        // ---- Gate compute: half the K range per thread ----
        float acc[4][4];
        #pragma unroll
        for (int u = 0; u < 4; u++) {
            float bv = (kh == 0) ? bias_s[j0 + u] : 0.0f;
            #pragma unroll
            for (int v = 0; v < 4; v++) acc[u][v] = bv;
        }
        const float* wp = w_s + j0;
        const float* vp = xh_s + rr0;
        #pragma unroll 4
        for (int k = kbeg; k < kend; k++) {
            float4 w  = *(const float4*)(wp + k * Gg);
            float4 hv = *(const float4*)(vp + k * ROWS);
            FMA16(w, hv)
        }
        // In-warp split-K reduction (pair lanes differ in bit 0)
        #pragma unroll
        for (int u = 0; u < 4; u++) {
            #pragma unroll
            for (int v = 0; v < 4; v++)
                acc[u][v] += __shfl_xor_sync(0xffffffffu, acc[u][v], 1);
        }
        // Each parity stores 2 of the 4 gate rows of the tile
        if (store_ok) {
            const int u0 = 2 * kh;
            *(float4*)(gates_s + (j0 + u0) * ROWS + rr0) =
                make_float4(acc[u0][0], acc[u0][1], acc[u0][2], acc[u0][3]);
            *(float4*)(gates_s + (j0 + u0 + 1) * ROWS + rr0) =
                make_float4(acc[u0+1][0], acc[u0+1][1], acc[u0+1][2], acc[u0+1][3]);
        }
        __syncthreads();   // gates ready; all xh reads of step t complete

        // Commit prefetched x(t+1) into x rows of xh
        if (pf_ok && t + 1 < Tt) xh_s[pk * ROWS + pr] = pf;

        // ---- Epilogue: activations + cell/hidden update (h -> xh rows 25..74) ----
        for (int i = tid; i < Hh * ROWS; i += NTH) {
            float gi = gates_s[i];
            float gf = gates_s[Hh * ROWS + i];
            float gg = gates_s[2 * Hh * ROWS + i];
            float go = gates_s[3 * Hh * ROWS + i];
            float iv = sigf(gi);
            float fv = sigf(gf);
            float gv = tanh_fast(gg);
            float ov = sigf(go);
            float c  = fmaf(fv, c_s[i], iv * gv);
            c_s[i] = c;
            xh_s[INP * ROWS + i] = ov * tanh_fast(c);
        }
        __syncthreads();   // h, c, x(t+1) ready for next step
    }

    // ---- Head: out[r] = h_last[r,:] . lin_w + lin_b ----
    for (int r = tid; r < ROWS; r += NTH) {
        if (row0 + r < Bsz) {
            float s = lin_b[0];
            #pragma unroll
            for (int m = 0; m < Hh; m++)
                s = fmaf(xh_s[(INP + m) * ROWS + r], lin_w[m], s);
            out[row0 + r] = s;
        }
    }
}

extern "C" void kernel_launch(void* const* d_in, const int* in_sizes, int n_in,
                              void* d_out, int out_size)
{
    const size_t smem_bytes =
        (size_t)(KTOT * Gg + Gg + KTOT * ROWS + Hh * ROWS + Gg * ROWS + 16)
        * sizeof(float);   // ~97.3 KB
    cudaFuncSetAttribute(bayes_lstm_kernel,
                         cudaFuncAttributeMaxDynamicSharedMemorySize,
                         (int)smem_bytes);
    bayes_lstm_kernel<<<GRID, NTH, smem_bytes>>>(
        (const float*)d_in[0],  (const float*)d_in[1],  (const float*)d_in[2],
        (const float*)d_in[3],  (const float*)d_in[4],  (const float*)d_in[5],
        (const float*)d_in[6],  (const float*)d_in[7],  (const float*)d_in[8],
        (const float*)d_in[9],  (const float*)d_in[10], (const float*)d_in[11],
        (float*)d_out);
}